// round 13
// baseline (speedup 1.0000x reference)
#include <cuda_runtime.h>
#include <cuda_bf16.h>
#include <cstdint>
#include <cstddef>

// ============================================================================
// out[16384,2048] = (x @ W^T) * (1/sqrt(2048)) + 0.1*b
// tcgen05 path (sm_103a): x = hi + lo (bf16 split), 64-iteration loop:
//   it  0..31 : bf16  hi_x * hi_w              (KC=64)
//   it 32..47 : e4m3 (hi_x*2^-4) * (lo_w*2^4)  (KC=128) = hi_x*lo_w
//   it 48..63 : e4m3 (lo_x*2^4) * (hi_w*2^-4)           = lo_x*hi_w
// R12: cta_group::2 MMA. Pair-tile 256(M) x 512(N), cluster (2,1,1).
// Per CTA/iter: A 16KB (its 128 M-rows) + B 32KB (its 256 N-rows) -> chip L2
// traffic 2.1GB -> 1.5GB (R11 was LTS-cap-bound). Warp-specialized control:
// tid0 producer (local), tid64 forwarder (FULL->RDY arrive), rank0 tid32 MMA
// issuer; stage release via cg2 commit-multicast (both CTAs, local CB).
// Fallback path (plain sm_103 pass): SIMT fp32 GEMM, same launch config.
// ============================================================================

#if defined(__CUDA_ARCH_FEAT_SM103_ALL) || defined(__CUDA_ARCH_FEAT_SM100_ALL) \
 || defined(__CUDA_ARCH_FEAT_SM101_ALL) \
 || (defined(__CUDA_ARCH_SPECIFIC__) && (__CUDA_ARCH_SPECIFIC__ >= 1000)) \
 || (defined(__CUDA_ARCH_FAMILY_SPECIFIC__) && (__CUDA_ARCH_FAMILY_SPECIFIC__ >= 1000))
#define HAS_TCGEN05 1
#else
#define HAS_TCGEN05 0
#endif

#define N_ROWS 16384
#define D_IN   2048
#define D_OUT  2048

#define TMSUB 128                   // M rows per CTA
#define TMP   256                   // M per pair
#define TNP   512                   // N per pair
#define NITER 64                    // 32 bf16 + 16 fp8 + 16 fp8
#define NSTAGE 3

#define A_UNIT 16384                // 128 rows x 128B (bf16 KC=64 / e4m3 KC=128)
#define B_UNIT 65536                // 512 rows x 128B (full pair B unit)
#define B_HALF 32768                // per-CTA half (256 rows)
#define STAGE_BYTES (A_UNIT + B_HALF)        // 49152
#define SMEM_TMEMPTR 0
#define SMEM_BAR     64   // FULL 0,8,16 | CB 24,32,40 | RDY 48,56,64 | FINAL 72
#define SMEM_STAGE0  1024
#define SMEM_TOTAL   (SMEM_STAGE0 + NSTAGE * STAGE_BYTES)  // 148480

#define TMEM_COLS 512

// idesc: [4:6) c=F32=1, [7:10) a_fmt, [10:13) b_fmt, [17:23) N>>3, [24:29) M>>4
// cg2: M=256 -> 16<<24, N=256 per dispatch -> 32<<17 (matches cg2 bf16 example)
#define IDESC_F16_CG2 ((1u << 4) | (1u << 7) | (1u << 10) | (32u << 17) | (16u << 24))
#define IDESC_F8_CG2  ((1u << 4) | (0u << 7) | (0u << 10) | (32u << 17) | (16u << 24))

#define SHI 0.0625f
#define SLO 16.0f

// ---------------- scratch (device globals: allocation-free) ----------------
// g_X: per 128-row tile, 64 units (0..31 bf16-hi, 32..47 hi8, 48..63 lo8).
// g_W: per 512-row tn-tile, 64 units of 64KB; rows permuted blocks [0,2,1,3]
//      so each cg2 rank's half is contiguous 32KB.
__device__ __align__(128) unsigned char g_X[(size_t)(N_ROWS / TMSUB) * 64 * A_UNIT]; // 128 MB
__device__ __align__(128) unsigned char g_W[(size_t)(D_OUT / TNP)   * 64 * B_UNIT];  // 16 MB

// ---------------- portable helpers (sm_90+) ----------------
__device__ __forceinline__ uint32_t smem_u32(const void* p) {
    uint32_t a;
    asm("{ .reg .u64 t; cvta.to.shared.u64 t, %1; cvt.u32.u64 %0, t; }" : "=r"(a) : "l"(p));
    return a;
}

__device__ __forceinline__ void mbar_init(uint32_t mbar, uint32_t count) {
    asm volatile("mbarrier.init.shared.b64 [%0], %1;" :: "r"(mbar), "r"(count) : "memory");
}

__device__ __forceinline__ void mbar_expect_tx(uint32_t mbar, uint32_t bytes) {
    asm volatile("mbarrier.arrive.expect_tx.shared.b64 _, [%0], %1;"
                 :: "r"(mbar), "r"(bytes) : "memory");
}

__device__ __forceinline__ void mbar_wait(uint32_t mbar, uint32_t parity) {
    asm volatile(
        "{\n\t"
        ".reg .pred P;\n\t"
        "WAIT_%=:\n\t"
        "mbarrier.try_wait.parity.acquire.cta.shared::cta.b64 P, [%0], %1, 0x989680;\n\t"
        "@!P bra WAIT_%=;\n\t"
        "}\n"
        :: "r"(mbar), "r"(parity) : "memory");
}

__device__ __forceinline__ void mbar_wait_cluster(uint32_t mbar, uint32_t parity) {
    asm volatile(
        "{\n\t"
        ".reg .pred P;\n\t"
        "WAITC_%=:\n\t"
        "mbarrier.try_wait.parity.acquire.cluster.shared::cta.b64 P, [%0], %1, 0x989680;\n\t"
        "@!P bra WAITC_%=;\n\t"
        "}\n"
        :: "r"(mbar), "r"(parity) : "memory");
}

__device__ __forceinline__ void bulk_g2s(uint32_t dst_smem, const void* src_gmem,
                                         uint32_t bytes, uint32_t mbar) {
    asm volatile(
        "cp.async.bulk.shared::cluster.global.mbarrier::complete_tx::bytes [%0], [%1], %2, [%3];"
        :: "r"(dst_smem), "l"(src_gmem), "r"(bytes), "r"(mbar) : "memory");
}

// Arrive on rank-0's barrier at the same SMEM offset (works from either rank).
__device__ __forceinline__ void remote_arrive_rank0(uint32_t local_mbar) {
    asm volatile(
        "{\n\t"
        ".reg .b32 r;\n\t"
        "mapa.shared::cluster.u32 r, %0, 0;\n\t"
        "mbarrier.arrive.release.cluster.shared::cluster.b64 _, [r];\n\t"
        "}"
        :: "r"(local_mbar) : "memory");
}

// 64-bit SMEM matrix descriptor, SW128, Blackwell (LBO=1, SBO=64)
__device__ __forceinline__ uint64_t make_desc(uint32_t smem_addr) {
    const uint64_t BASE = (uint64_t(2) << 61)
                        | (uint64_t(1) << 46)
                        | (uint64_t(64) << 32)
                        | (uint64_t(1) << 16);
    return BASE | ((uint64_t)(smem_addr >> 4) & 0x3FFF);
}

__device__ __forceinline__ uint16_t f2_e4m3x2(float hi, float lo) {
    uint16_t r;
    asm("cvt.rn.satfinite.e4m3x2.f32 %0, %1, %2;" : "=h"(r) : "f"(hi), "f"(lo));
    return r;
}

#if HAS_TCGEN05
// ---------------- 'a'-pass only wrappers ----------------
__device__ __forceinline__ void mma_f16_cg2(uint32_t d_tmem, uint64_t a_desc, uint64_t b_desc,
                                            uint32_t en) {
    asm volatile(
        "{\n\t"
        ".reg .pred p;\n\t"
        "setp.ne.u32 p, %5, 0;\n\t"
        "tcgen05.mma.cta_group::2.kind::f16 [%0], %1, %2, %3, "
        "{%4, %4, %4, %4, %4, %4, %4, %4}, p;\n\t"
        "}"
        :: "r"(d_tmem), "l"(a_desc), "l"(b_desc), "r"(IDESC_F16_CG2), "r"(0u), "r"(en)
        : "memory");
}

__device__ __forceinline__ void mma_f8_cg2(uint32_t d_tmem, uint64_t a_desc, uint64_t b_desc,
                                           uint32_t en) {
    asm volatile(
        "{\n\t"
        ".reg .pred p;\n\t"
        "setp.ne.u32 p, %5, 0;\n\t"
        "tcgen05.mma.cta_group::2.kind::f8f6f4 [%0], %1, %2, %3, "
        "{%4, %4, %4, %4, %4, %4, %4, %4}, p;\n\t"
        "}"
        :: "r"(d_tmem), "l"(a_desc), "l"(b_desc), "r"(IDESC_F8_CG2), "r"(0u), "r"(en)
        : "memory");
}

__device__ __forceinline__ void tcommit_cg2_mc(uint32_t mbar) {
    asm volatile(
        "tcgen05.commit.cta_group::2.mbarrier::arrive::one.shared::cluster.multicast::cluster.b64"
        " [%0], %1;"
        :: "r"(mbar), "h"((uint16_t)0x3) : "memory");
}

#define TLD_32X32B_X32(r, tmem_addr) \
    asm volatile( \
        "tcgen05.ld.sync.aligned.32x32b.x32.b32 " \
        "{%0, %1, %2, %3, %4, %5, %6, %7, " \
        " %8, %9, %10, %11, %12, %13, %14, %15, " \
        " %16, %17, %18, %19, %20, %21, %22, %23, " \
        " %24, %25, %26, %27, %28, %29, %30, %31}, [%32];" \
        : "=r"((r)[0]),  "=r"((r)[1]),  "=r"((r)[2]),  "=r"((r)[3]), \
          "=r"((r)[4]),  "=r"((r)[5]),  "=r"((r)[6]),  "=r"((r)[7]), \
          "=r"((r)[8]),  "=r"((r)[9]),  "=r"((r)[10]), "=r"((r)[11]), \
          "=r"((r)[12]), "=r"((r)[13]), "=r"((r)[14]), "=r"((r)[15]), \
          "=r"((r)[16]), "=r"((r)[17]), "=r"((r)[18]), "=r"((r)[19]), \
          "=r"((r)[20]), "=r"((r)[21]), "=r"((r)[22]), "=r"((r)[23]), \
          "=r"((r)[24]), "=r"((r)[25]), "=r"((r)[26]), "=r"((r)[27]), \
          "=r"((r)[28]), "=r"((r)[29]), "=r"((r)[30]), "=r"((r)[31]) \
        : "r"(tmem_addr))
#endif  // HAS_TCGEN05

// ============================================================================
// Conversion: fp32 -> bf16-hi + e4m3 hi8/lo8 tiles, SW128 swizzled.
// PERM=1 (W, TILE_R=512): rows reordered in 128-blocks [0,2,1,3] so each cg2
// rank's B half (dispatch0-block then dispatch1-block) is contiguous 32KB.
// ============================================================================
template <int TILE_R, int PERM>
__global__ void __launch_bounds__(256) convert_kernel(const float* __restrict__ src) {
    unsigned char* dstBase = (TILE_R == TMSUB) ? g_X : g_W;
    const int tk = blockIdx.x;   // superchunk (128 K-elems)
    const int tr = blockIdx.y;
    const size_t tile = (size_t)TILE_R * 128;
    unsigned char* base = dstBase + (size_t)tr * (64 * tile);
    unsigned char* hiB16a = base + (size_t)(2 * tk)     * tile;
    unsigned char* hiB16b = base + (size_t)(2 * tk + 1) * tile;
    unsigned char* hi8    = base + (size_t)(32 + tk)    * tile;
    unsigned char* lo8    = base + (size_t)(48 + tk)    * tile;

    const int quads = TILE_R * 32;
    for (int t = threadIdx.x; t < quads; t += 256) {
        const int r = t >> 5;
        const int q = t & 31;
        const float4 v = *(const float4*)(src + (size_t)(tr * TILE_R + r) * D_IN + tk * 128 + q * 4);

        int rs = r;
        if (PERM) {
            const int b = r >> 7;
            const int sb = ((b & 1) << 1) | (b >> 1);   // 0,1,2,3 -> 0,2,1,3
            rs = sb * 128 + (r & 127);
        }

        const __nv_bfloat16 h0 = __float2bfloat16(v.x);
        const __nv_bfloat16 h1 = __float2bfloat16(v.y);
        const __nv_bfloat16 h2 = __float2bfloat16(v.z);
        const __nv_bfloat16 h3 = __float2bfloat16(v.w);
        const float f0 = __bfloat162float(h0), f1 = __bfloat162float(h1);
        const float f2 = __bfloat162float(h2), f3 = __bfloat162float(h3);
        const float l0 = v.x - f0, l1 = v.y - f1, l2 = v.z - f2, l3 = v.w - f3;

        const uint32_t offB = (uint32_t)rs * 128u + (uint32_t)((q * 4) & 63) * 2u;
        const uint32_t swB = offB ^ ((offB >> 3) & 0x70);
        unsigned char* bt = (q < 16) ? hiB16a : hiB16b;
        uint2 hp;
        hp.x = ((uint32_t)__bfloat16_as_ushort(h1) << 16) | __bfloat16_as_ushort(h0);
        hp.y = ((uint32_t)__bfloat16_as_ushort(h3) << 16) | __bfloat16_as_ushort(h2);
        *(uint2*)(bt + swB) = hp;

        const uint32_t off8 = (uint32_t)rs * 128u + (uint32_t)q * 4u;
        const uint32_t sw8 = off8 ^ ((off8 >> 3) & 0x70);
        const uint32_t wHi = (uint32_t)f2_e4m3x2(f1 * SHI, f0 * SHI)
                           | ((uint32_t)f2_e4m3x2(f3 * SHI, f2 * SHI) << 16);
        const uint32_t wLo = (uint32_t)f2_e4m3x2(l1 * SLO, l0 * SLO)
                           | ((uint32_t)f2_e4m3x2(l3 * SLO, l2 * SLO) << 16);
        *(uint32_t*)(hi8 + sw8) = wHi;
        *(uint32_t*)(lo8 + sw8) = wLo;
    }
}

// iteration -> B/A tile unit index
__device__ __forceinline__ int b_unit(int j) {
    return j < 32 ? j : (j < 48 ? j + 16 : j - 16);
}

// ============================================================================
// GEMM: grid (8, 64) = (4 tn-tiles x 2 ranks, 64 tm-tiles), cluster (2,1,1),
// block 128. Pair computes 256x512.
// ============================================================================
__global__ __launch_bounds__(128, 1) __cluster_dims__(2, 1, 1)
void gemm_kernel(const float* __restrict__ x,
                 const float* __restrict__ w,
                 const float* __restrict__ bias,
                 float* __restrict__ out) {
#if HAS_TCGEN05
    (void)x; (void)w;
    extern __shared__ __align__(1024) unsigned char smem[];
    const uint32_t sb = smem_u32(smem);
    const int tid = threadIdx.x;
    const int wid = tid >> 5, lid = tid & 31;
    const int tn = blockIdx.x >> 1;   // 0..3
    const int tm = blockIdx.y;        // 0..63
    uint32_t rank;
    asm("mov.u32 %0, %%cluster_ctarank;" : "=r"(rank));

    const uint32_t FULL  = sb + SMEM_BAR + 0;
    const uint32_t CB    = sb + SMEM_BAR + 24;
    const uint32_t RDY   = sb + SMEM_BAR + 48;
    const uint32_t FINAL = sb + SMEM_BAR + 72;

    if (tid == 0) {
        #pragma unroll
        for (int i = 0; i < NSTAGE; i++) {
            mbar_init(FULL + i * 8, 1);
            mbar_init(CB + i * 8, 1);
            mbar_init(RDY + i * 8, 2);   // one arrive from each rank's forwarder
        }
        mbar_init(FINAL, 1);
        asm volatile("fence.proxy.async.shared::cta;" ::: "memory");
    }
    if (wid == 0) {
        asm volatile("tcgen05.alloc.cta_group::2.sync.aligned.shared::cta.b32 [%0], %1;"
                     :: "r"(sb + SMEM_TMEMPTR), "r"(TMEM_COLS) : "memory");
    }
    __syncthreads();
    uint32_t tmem;
    asm volatile("ld.shared.b32 %0, [%1];" : "=r"(tmem) : "r"(sb + SMEM_TMEMPTR));
    if (wid == 0)
        asm volatile("tcgen05.relinquish_alloc_permit.cta_group::2.sync.aligned;");

    // barriers + TMEM visible cluster-wide before cross-CTA traffic
    asm volatile("barrier.cluster.arrive.aligned;" ::: "memory");
    asm volatile("barrier.cluster.wait.aligned;" ::: "memory");

    if (tid == 0) {
        // ---------------- PRODUCER (fully local) ----------------
        const unsigned char* aSrc = g_X + (size_t)(tm * 2 + rank) * 64 * A_UNIT;
        const unsigned char* bSrc = g_W + (size_t)tn * 64 * B_UNIT + (size_t)rank * B_HALF;

        int cbPh[NSTAGE] = {0, 0, 0};
        for (int j = 0; j < NITER; j++) {
            const int s = j % NSTAGE;
            if (j >= NSTAGE) { mbar_wait(CB + s * 8, cbPh[s]); cbPh[s] ^= 1; }
            const uint32_t st = sb + SMEM_STAGE0 + s * STAGE_BYTES;
            mbar_expect_tx(FULL + s * 8, STAGE_BYTES);
            bulk_g2s(st,          aSrc + (size_t)j * A_UNIT, A_UNIT, FULL + s * 8);
            bulk_g2s(st + A_UNIT, bSrc + (size_t)b_unit(j) * B_UNIT, B_HALF, FULL + s * 8);
        }
    } else if (tid == 64) {
        // ---------------- FORWARDER: local FULL -> rank0 RDY ----------------
        int fullPh[NSTAGE] = {0, 0, 0};
        for (int j = 0; j < NITER; j++) {
            const int s = j % NSTAGE;
            mbar_wait(FULL + s * 8, fullPh[s]); fullPh[s] ^= 1;
            remote_arrive_rank0(RDY + s * 8);
        }
    } else if (tid == 32 && rank == 0) {
        // ---------------- MMA ISSUER (rank 0 only) ----------------
        int rdyPh[NSTAGE] = {0, 0, 0};
        for (int it = 0; it < NITER; it++) {
            const int s = it % NSTAGE;
            mbar_wait_cluster(RDY + s * 8, rdyPh[s]); rdyPh[s] ^= 1;   // both halves landed

            const uint32_t st = sb + SMEM_STAGE0 + s * STAGE_BYTES;
            const uint64_t dA = make_desc(st);
            const uint64_t dB = make_desc(st + A_UNIT);
            const uint64_t NH = 1024;   // dispatch1 B block: +128 rows x 128B = 16384B/16

            if (it < 32) {
                #pragma unroll
                for (int ks = 0; ks < 4; ks++) {
                    const uint64_t ko = (uint64_t)(ks * 2);   // +32B = 16 bf16 K-elems
                    const uint32_t acc = (it | ks) ? 1u : 0u;
                    mma_f16_cg2(tmem +   0, dA + ko, dB + ko,      acc);  // N[0:256)
                    mma_f16_cg2(tmem + 256, dA + ko, dB + NH + ko, acc);  // N[256:512)
                }
            } else {
                #pragma unroll
                for (int ks = 0; ks < 4; ks++) {
                    const uint64_t ko = (uint64_t)(ks * 2);   // +32B = 32 e4m3 K-elems
                    mma_f8_cg2(tmem +   0, dA + ko, dB + ko,      1u);
                    mma_f8_cg2(tmem + 256, dA + ko, dB + NH + ko, 1u);
                }
            }
            tcommit_cg2_mc(CB + s * 8);   // releases stage s in BOTH CTAs on retire
        }
        tcommit_cg2_mc(FINAL);
    }

    mbar_wait(FINAL, 0);
    asm volatile("tcgen05.fence::after_thread_sync;" ::: "memory");

    // ---- epilogue: this CTA's 128 rows x 512 cols, in two 256-col chunks ----
    const int r = wid * 32 + lid;
    uint32_t* epi = (uint32_t*)(smem + SMEM_STAGE0);   // 128KB staging (stages dead)
    const float scale = 0.022097086912079608f;         // 1/sqrt(2048)

    #pragma unroll
    for (int nh = 0; nh < 2; nh++) {
        #pragma unroll
        for (int cb = 0; cb < 256; cb += 32) {
            uint32_t regs[32];
            TLD_32X32B_X32(regs, tmem + nh * 256 + cb);
            asm volatile("tcgen05.wait::ld.sync.aligned;" ::: "memory");
            #pragma unroll
            for (int j = 0; j < 32; j++) {
                const int c = cb + j;
                epi[r * 256 + (c ^ (r & 31))] = regs[j];
            }
        }
        __syncthreads();

        float* outBase = out + (size_t)(tm * TMP + rank * TMSUB) * D_OUT
                       + (size_t)tn * TNP + nh * 256;
        const float* bch = bias + tn * TNP + nh * 256;
        #pragma unroll 4
        for (int itl = 0; itl < (TMSUB * 256) / 128; itl++) {
            const int i = itl * 128 + tid;
            const int rr = i >> 8;
            const int c = i & 255;
            const float v = __uint_as_float(epi[rr * 256 + (c ^ (rr & 31))]);
            outBase[(size_t)rr * D_OUT + c] = v * scale + 0.1f * __ldg(bch + c);
        }
        __syncthreads();
    }

    if (wid == 0) {
        asm volatile("tcgen05.dealloc.cta_group::2.sync.aligned.b32 %0, %1;"
                     :: "r"(tmem), "r"(TMEM_COLS));
    }
    // no CTA exits while its SMEM may still be referenced by the pair
    asm volatile("barrier.cluster.arrive.aligned;" ::: "memory");
    asm volatile("barrier.cluster.wait.aligned;" ::: "memory");

#else  // ======================= SIMT fp32 fallback =========================
    extern __shared__ __align__(16) float fsm[];
    float* ws = fsm;                 // 32 cols x 128 k  (16 KB)
    float* xs = fsm + 32 * 128;      // 128 rows x 132   (66 KB)
    const int tid = threadIdx.x;
    const int tn = blockIdx.x >> 1, rk = blockIdx.x & 1, tm = blockIdx.y;
    const float scale = 0.022097086912079608f;
    const int rowBase = tm * TMP + rk * TMSUB;
    const int row = rowBase + tid;

    for (int nc = 0; nc < TNP / 32; nc++) {
        const int cb = tn * TNP + nc * 32;
        float acc[32];
        #pragma unroll
        for (int c = 0; c < 32; c++) acc[c] = 0.0f;

        for (int kb = 0; kb < D_IN; kb += 128) {
            __syncthreads();
            for (int i = tid; i < 32 * 128; i += 128)
                ws[i] = w[(size_t)(cb + (i >> 7)) * D_IN + kb + (i & 127)];
            for (int i = tid; i < 128 * 128; i += 128)
                xs[(i >> 7) * 132 + (i & 127)] = x[(size_t)(rowBase + (i >> 7)) * D_IN + kb + (i & 127)];
            __syncthreads();

            #pragma unroll 2
            for (int k4 = 0; k4 < 32; k4++) {
                const float4 xv = *(const float4*)&xs[tid * 132 + k4 * 4];
                #pragma unroll
                for (int c = 0; c < 32; c++) {
                    const float4 wv = *(const float4*)&ws[(c << 7) + (k4 << 2)];
                    acc[c] += xv.x * wv.x + xv.y * wv.y + xv.z * wv.z + xv.w * wv.w;
                }
            }
        }
        #pragma unroll
        for (int c = 0; c < 32; c++)
            out[(size_t)row * D_OUT + cb + c] = acc[c] * scale + 0.1f * bias[cb + c];
    }
#endif
}

// ============================================================================
extern "C" void kernel_launch(void* const* d_in, const int* in_sizes, int n_in,
                              void* d_out, int out_size) {
    const float* x = (const float*)d_in[0];
    const float* w = (const float*)d_in[1];
    const float* b = (const float*)d_in[2];
    float* out = (float*)d_out;

    cudaFuncSetAttribute(gemm_kernel, cudaFuncAttributeMaxDynamicSharedMemorySize, SMEM_TOTAL);

    convert_kernel<TMSUB, 0><<<dim3(D_IN / 128, N_ROWS / TMSUB), 256>>>(x);  // x -> g_X
    convert_kernel<TNP, 1> <<<dim3(D_IN / 128, D_OUT / TNP),     256>>>(w);  // W -> g_W (perm)
    gemm_kernel<<<dim3((D_OUT / TNP) * 2, N_ROWS / TMP), 128, SMEM_TOTAL>>>(x, w, b, out);
}

// round 14
// speedup vs baseline: 1.0430x; 1.0430x over previous
#include <cuda_runtime.h>
#include <cuda_bf16.h>
#include <cstdint>
#include <cstddef>

// ============================================================================
// out[16384,2048] = (x @ W^T) * (1/sqrt(2048)) + 0.1*b
// tcgen05 path (sm_103a): x = hi + lo (bf16 split), 64-iteration loop:
//   it  0..31 : bf16  hi_x * hi_w              (KC=64)
//   it 32..47 : e4m3 (hi_x*2^-4) * (lo_w*2^4)  (KC=128) = hi_x*lo_w
//   it 48..63 : e4m3 (lo_x*2^4) * (hi_w*2^-4)           = lo_x*hi_w
// cta_group::2 MMA, pair-tile 256(M) x 512(N), cluster (2,1,1).
// R14 vs R13: NSTAGE 3 -> 4. The cg2 per-stage latency loop (TMA land ->
// forwarder remote-arrive -> cluster wait -> MMA -> commit-multicast ->
// producer) is ~2800 cyc; 3-stage slack (3072) was marginal -> latency-bound.
// 4-stage slack (4096) restores throughput-bound operation. Same SMEM budget.
// Fallback path (plain sm_103 pass): SIMT fp32 GEMM, same launch config.
// ============================================================================

#if defined(__CUDA_ARCH_FEAT_SM103_ALL) || defined(__CUDA_ARCH_FEAT_SM100_ALL) \
 || defined(__CUDA_ARCH_FEAT_SM101_ALL) \
 || (defined(__CUDA_ARCH_SPECIFIC__) && (__CUDA_ARCH_SPECIFIC__ >= 1000)) \
 || (defined(__CUDA_ARCH_FAMILY_SPECIFIC__) && (__CUDA_ARCH_FAMILY_SPECIFIC__ >= 1000))
#define HAS_TCGEN05 1
#else
#define HAS_TCGEN05 0
#endif

#define N_ROWS 16384
#define D_IN   2048
#define D_OUT  2048

#define TMSUB 128                   // M rows per CTA
#define TMP   256                   // M per pair
#define TNP   512                   // N per pair
#define NITER 64                    // 32 bf16 + 16 fp8 + 16 fp8
#define NSTAGE 4

#define A_UNIT 16384                // 128 rows x 128B (bf16 KC=64 / e4m3 KC=128)
#define B_UNIT 65536                // 512 rows x 128B (full pair B unit)
#define B_HALF 32768                // per-CTA half (256 rows)
#define STAGE_BYTES (A_UNIT + B_HALF)        // 49152
#define SMEM_TMEMPTR 0
#define SMEM_BAR     64   // FULL +0..24 | CB +32..56 | RDY +64..88 | FINAL +96
#define SMEM_STAGE0  1024
#define SMEM_TOTAL   (SMEM_STAGE0 + NSTAGE * STAGE_BYTES)  // 197632

#define TMEM_COLS 512

// idesc: [4:6) c=F32=1, [7:10) a_fmt, [10:13) b_fmt, [17:23) N>>3, [24:29) M>>4
// cg2: M=256 -> 16<<24, N=256 per dispatch -> 32<<17
#define IDESC_F16_CG2 ((1u << 4) | (1u << 7) | (1u << 10) | (32u << 17) | (16u << 24))
#define IDESC_F8_CG2  ((1u << 4) | (0u << 7) | (0u << 10) | (32u << 17) | (16u << 24))

#define SHI 0.0625f
#define SLO 16.0f

// ---------------- scratch (device globals: allocation-free) ----------------
// g_X: per 128-row tile, 64 units (0..31 bf16-hi, 32..47 hi8, 48..63 lo8).
// g_W: per 512-row tn-tile, 64 units of 64KB; rows permuted in 128-blocks
//      [0,2,1,3] so each cg2 rank's half is contiguous 32KB.
__device__ __align__(128) unsigned char g_X[(size_t)(N_ROWS / TMSUB) * 64 * A_UNIT]; // 128 MB
__device__ __align__(128) unsigned char g_W[(size_t)(D_OUT / TNP)   * 64 * B_UNIT];  // 16 MB

// ---------------- portable helpers (sm_90+) ----------------
__device__ __forceinline__ uint32_t smem_u32(const void* p) {
    uint32_t a;
    asm("{ .reg .u64 t; cvta.to.shared.u64 t, %1; cvt.u32.u64 %0, t; }" : "=r"(a) : "l"(p));
    return a;
}

__device__ __forceinline__ void mbar_init(uint32_t mbar, uint32_t count) {
    asm volatile("mbarrier.init.shared.b64 [%0], %1;" :: "r"(mbar), "r"(count) : "memory");
}

__device__ __forceinline__ void mbar_expect_tx(uint32_t mbar, uint32_t bytes) {
    asm volatile("mbarrier.arrive.expect_tx.shared.b64 _, [%0], %1;"
                 :: "r"(mbar), "r"(bytes) : "memory");
}

__device__ __forceinline__ void mbar_wait(uint32_t mbar, uint32_t parity) {
    asm volatile(
        "{\n\t"
        ".reg .pred P;\n\t"
        "WAIT_%=:\n\t"
        "mbarrier.try_wait.parity.acquire.cta.shared::cta.b64 P, [%0], %1, 0x989680;\n\t"
        "@!P bra WAIT_%=;\n\t"
        "}\n"
        :: "r"(mbar), "r"(parity) : "memory");
}

__device__ __forceinline__ void mbar_wait_cluster(uint32_t mbar, uint32_t parity) {
    asm volatile(
        "{\n\t"
        ".reg .pred P;\n\t"
        "WAITC_%=:\n\t"
        "mbarrier.try_wait.parity.acquire.cluster.shared::cta.b64 P, [%0], %1, 0x989680;\n\t"
        "@!P bra WAITC_%=;\n\t"
        "}\n"
        :: "r"(mbar), "r"(parity) : "memory");
}

__device__ __forceinline__ void bulk_g2s(uint32_t dst_smem, const void* src_gmem,
                                         uint32_t bytes, uint32_t mbar) {
    asm volatile(
        "cp.async.bulk.shared::cluster.global.mbarrier::complete_tx::bytes [%0], [%1], %2, [%3];"
        :: "r"(dst_smem), "l"(src_gmem), "r"(bytes), "r"(mbar) : "memory");
}

// Arrive on rank-0's barrier at the same SMEM offset.
__device__ __forceinline__ void remote_arrive_rank0(uint32_t local_mbar) {
    asm volatile(
        "{\n\t"
        ".reg .b32 r;\n\t"
        "mapa.shared::cluster.u32 r, %0, 0;\n\t"
        "mbarrier.arrive.release.cluster.shared::cluster.b64 _, [r];\n\t"
        "}"
        :: "r"(local_mbar) : "memory");
}

// 64-bit SMEM matrix descriptor, SW128, Blackwell (LBO=1, SBO=64)
__device__ __forceinline__ uint64_t make_desc(uint32_t smem_addr) {
    const uint64_t BASE = (uint64_t(2) << 61)
                        | (uint64_t(1) << 46)
                        | (uint64_t(64) << 32)
                        | (uint64_t(1) << 16);
    return BASE | ((uint64_t)(smem_addr >> 4) & 0x3FFF);
}

__device__ __forceinline__ uint16_t f2_e4m3x2(float hi, float lo) {
    uint16_t r;
    asm("cvt.rn.satfinite.e4m3x2.f32 %0, %1, %2;" : "=h"(r) : "f"(hi), "f"(lo));
    return r;
}

#if HAS_TCGEN05
// ---------------- 'a'-pass only wrappers ----------------
__device__ __forceinline__ void mma_f16_cg2(uint32_t d_tmem, uint64_t a_desc, uint64_t b_desc,
                                            uint32_t en) {
    asm volatile(
        "{\n\t"
        ".reg .pred p;\n\t"
        "setp.ne.u32 p, %5, 0;\n\t"
        "tcgen05.mma.cta_group::2.kind::f16 [%0], %1, %2, %3, "
        "{%4, %4, %4, %4, %4, %4, %4, %4}, p;\n\t"
        "}"
        :: "r"(d_tmem), "l"(a_desc), "l"(b_desc), "r"(IDESC_F16_CG2), "r"(0u), "r"(en)
        : "memory");
}

__device__ __forceinline__ void mma_f8_cg2(uint32_t d_tmem, uint64_t a_desc, uint64_t b_desc,
                                           uint32_t en) {
    asm volatile(
        "{\n\t"
        ".reg .pred p;\n\t"
        "setp.ne.u32 p, %5, 0;\n\t"
        "tcgen05.mma.cta_group::2.kind::f8f6f4 [%0], %1, %2, %3, "
        "{%4, %4, %4, %4, %4, %4, %4, %4}, p;\n\t"
        "}"
        :: "r"(d_tmem), "l"(a_desc), "l"(b_desc), "r"(IDESC_F8_CG2), "r"(0u), "r"(en)
        : "memory");
}

__device__ __forceinline__ void tcommit_cg2_mc(uint32_t mbar) {
    asm volatile(
        "tcgen05.commit.cta_group::2.mbarrier::arrive::one.shared::cluster.multicast::cluster.b64"
        " [%0], %1;"
        :: "r"(mbar), "h"((uint16_t)0x3) : "memory");
}

#define TLD_32X32B_X32(r, tmem_addr) \
    asm volatile( \
        "tcgen05.ld.sync.aligned.32x32b.x32.b32 " \
        "{%0, %1, %2, %3, %4, %5, %6, %7, " \
        " %8, %9, %10, %11, %12, %13, %14, %15, " \
        " %16, %17, %18, %19, %20, %21, %22, %23, " \
        " %24, %25, %26, %27, %28, %29, %30, %31}, [%32];" \
        : "=r"((r)[0]),  "=r"((r)[1]),  "=r"((r)[2]),  "=r"((r)[3]), \
          "=r"((r)[4]),  "=r"((r)[5]),  "=r"((r)[6]),  "=r"((r)[7]), \
          "=r"((r)[8]),  "=r"((r)[9]),  "=r"((r)[10]), "=r"((r)[11]), \
          "=r"((r)[12]), "=r"((r)[13]), "=r"((r)[14]), "=r"((r)[15]), \
          "=r"((r)[16]), "=r"((r)[17]), "=r"((r)[18]), "=r"((r)[19]), \
          "=r"((r)[20]), "=r"((r)[21]), "=r"((r)[22]), "=r"((r)[23]), \
          "=r"((r)[24]), "=r"((r)[25]), "=r"((r)[26]), "=r"((r)[27]), \
          "=r"((r)[28]), "=r"((r)[29]), "=r"((r)[30]), "=r"((r)[31]) \
        : "r"(tmem_addr))
#endif  // HAS_TCGEN05

// ============================================================================
// Conversion: fp32 -> bf16-hi + e4m3 hi8/lo8 tiles, SW128 swizzled.
// PERM=1 (W, TILE_R=512): rows reordered in 128-blocks [0,2,1,3].
// ============================================================================
template <int TILE_R, int PERM>
__global__ void __launch_bounds__(256) convert_kernel(const float* __restrict__ src) {
    unsigned char* dstBase = (TILE_R == TMSUB) ? g_X : g_W;
    const int tk = blockIdx.x;   // superchunk (128 K-elems)
    const int tr = blockIdx.y;
    const size_t tile = (size_t)TILE_R * 128;
    unsigned char* base = dstBase + (size_t)tr * (64 * tile);
    unsigned char* hiB16a = base + (size_t)(2 * tk)     * tile;
    unsigned char* hiB16b = base + (size_t)(2 * tk + 1) * tile;
    unsigned char* hi8    = base + (size_t)(32 + tk)    * tile;
    unsigned char* lo8    = base + (size_t)(48 + tk)    * tile;

    const int quads = TILE_R * 32;
    for (int t = threadIdx.x; t < quads; t += 256) {
        const int r = t >> 5;
        const int q = t & 31;
        const float4 v = *(const float4*)(src + (size_t)(tr * TILE_R + r) * D_IN + tk * 128 + q * 4);

        int rs = r;
        if (PERM) {
            const int b = r >> 7;
            const int sb2 = ((b & 1) << 1) | (b >> 1);   // 0,1,2,3 -> 0,2,1,3
            rs = sb2 * 128 + (r & 127);
        }

        const __nv_bfloat16 h0 = __float2bfloat16(v.x);
        const __nv_bfloat16 h1 = __float2bfloat16(v.y);
        const __nv_bfloat16 h2 = __float2bfloat16(v.z);
        const __nv_bfloat16 h3 = __float2bfloat16(v.w);
        const float f0 = __bfloat162float(h0), f1 = __bfloat162float(h1);
        const float f2 = __bfloat162float(h2), f3 = __bfloat162float(h3);
        const float l0 = v.x - f0, l1 = v.y - f1, l2 = v.z - f2, l3 = v.w - f3;

        const uint32_t offB = (uint32_t)rs * 128u + (uint32_t)((q * 4) & 63) * 2u;
        const uint32_t swB = offB ^ ((offB >> 3) & 0x70);
        unsigned char* bt = (q < 16) ? hiB16a : hiB16b;
        uint2 hp;
        hp.x = ((uint32_t)__bfloat16_as_ushort(h1) << 16) | __bfloat16_as_ushort(h0);
        hp.y = ((uint32_t)__bfloat16_as_ushort(h3) << 16) | __bfloat16_as_ushort(h2);
        *(uint2*)(bt + swB) = hp;

        const uint32_t off8 = (uint32_t)rs * 128u + (uint32_t)q * 4u;
        const uint32_t sw8 = off8 ^ ((off8 >> 3) & 0x70);
        const uint32_t wHi = (uint32_t)f2_e4m3x2(f1 * SHI, f0 * SHI)
                           | ((uint32_t)f2_e4m3x2(f3 * SHI, f2 * SHI) << 16);
        const uint32_t wLo = (uint32_t)f2_e4m3x2(l1 * SLO, l0 * SLO)
                           | ((uint32_t)f2_e4m3x2(l3 * SLO, l2 * SLO) << 16);
        *(uint32_t*)(hi8 + sw8) = wHi;
        *(uint32_t*)(lo8 + sw8) = wLo;
    }
}

// iteration -> B/A tile unit index
__device__ __forceinline__ int b_unit(int j) {
    return j < 32 ? j : (j < 48 ? j + 16 : j - 16);
}

// ============================================================================
// GEMM: grid (8, 64) = (4 tn-tiles x 2 ranks, 64 tm-tiles), cluster (2,1,1),
// block 128. Pair computes 256x512.
// ============================================================================
__global__ __launch_bounds__(128, 1) __cluster_dims__(2, 1, 1)
void gemm_kernel(const float* __restrict__ x,
                 const float* __restrict__ w,
                 const float* __restrict__ bias,
                 float* __restrict__ out) {
#if HAS_TCGEN05
    (void)x; (void)w;
    extern __shared__ __align__(1024) unsigned char smem[];
    const uint32_t sb = smem_u32(smem);
    const int tid = threadIdx.x;
    const int wid = tid >> 5, lid = tid & 31;
    const int tn = blockIdx.x >> 1;   // 0..3
    const int tm = blockIdx.y;        // 0..63
    uint32_t rank;
    asm("mov.u32 %0, %%cluster_ctarank;" : "=r"(rank));

    const uint32_t FULL  = sb + SMEM_BAR + 0;
    const uint32_t CB    = sb + SMEM_BAR + 32;
    const uint32_t RDY   = sb + SMEM_BAR + 64;
    const uint32_t FINAL = sb + SMEM_BAR + 96;

    if (tid == 0) {
        #pragma unroll
        for (int i = 0; i < NSTAGE; i++) {
            mbar_init(FULL + i * 8, 1);
            mbar_init(CB + i * 8, 1);
            mbar_init(RDY + i * 8, 2);   // one arrive from each rank's forwarder
        }
        mbar_init(FINAL, 1);
        asm volatile("fence.proxy.async.shared::cta;" ::: "memory");
    }
    if (wid == 0) {
        asm volatile("tcgen05.alloc.cta_group::2.sync.aligned.shared::cta.b32 [%0], %1;"
                     :: "r"(sb + SMEM_TMEMPTR), "r"(TMEM_COLS) : "memory");
    }
    __syncthreads();
    uint32_t tmem;
    asm volatile("ld.shared.b32 %0, [%1];" : "=r"(tmem) : "r"(sb + SMEM_TMEMPTR));
    if (wid == 0)
        asm volatile("tcgen05.relinquish_alloc_permit.cta_group::2.sync.aligned;");

    // barriers + TMEM visible cluster-wide before cross-CTA traffic
    asm volatile("barrier.cluster.arrive.aligned;" ::: "memory");
    asm volatile("barrier.cluster.wait.aligned;" ::: "memory");

    if (tid == 0) {
        // ---------------- PRODUCER (fully local) ----------------
        const unsigned char* aSrc = g_X + (size_t)(tm * 2 + rank) * 64 * A_UNIT;
        const unsigned char* bSrc = g_W + (size_t)tn * 64 * B_UNIT + (size_t)rank * B_HALF;

        int cbPh[NSTAGE] = {0, 0, 0, 0};
        for (int j = 0; j < NITER; j++) {
            const int s = j % NSTAGE;
            if (j >= NSTAGE) { mbar_wait(CB + s * 8, cbPh[s]); cbPh[s] ^= 1; }
            const uint32_t st = sb + SMEM_STAGE0 + s * STAGE_BYTES;
            mbar_expect_tx(FULL + s * 8, STAGE_BYTES);
            bulk_g2s(st,          aSrc + (size_t)j * A_UNIT, A_UNIT, FULL + s * 8);
            bulk_g2s(st + A_UNIT, bSrc + (size_t)b_unit(j) * B_UNIT, B_HALF, FULL + s * 8);
        }
    } else if (tid == 64) {
        // ---------------- FORWARDER: local FULL -> rank0 RDY ----------------
        int fullPh[NSTAGE] = {0, 0, 0, 0};
        for (int j = 0; j < NITER; j++) {
            const int s = j % NSTAGE;
            mbar_wait(FULL + s * 8, fullPh[s]); fullPh[s] ^= 1;
            remote_arrive_rank0(RDY + s * 8);
        }
    } else if (tid == 32 && rank == 0) {
        // ---------------- MMA ISSUER (rank 0 only) ----------------
        int rdyPh[NSTAGE] = {0, 0, 0, 0};
        for (int it = 0; it < NITER; it++) {
            const int s = it % NSTAGE;
            mbar_wait_cluster(RDY + s * 8, rdyPh[s]); rdyPh[s] ^= 1;   // both halves landed

            const uint32_t st = sb + SMEM_STAGE0 + s * STAGE_BYTES;
            const uint64_t dA = make_desc(st);
            const uint64_t dB = make_desc(st + A_UNIT);
            const uint64_t NH = 1024;   // dispatch1 B block: +128 rows x 128B = 16384B/16

            if (it < 32) {
                #pragma unroll
                for (int ks = 0; ks < 4; ks++) {
                    const uint64_t ko = (uint64_t)(ks * 2);   // +32B = 16 bf16 K-elems
                    const uint32_t acc = (it | ks) ? 1u : 0u;
                    mma_f16_cg2(tmem +   0, dA + ko, dB + ko,      acc);  // N[0:256)
                    mma_f16_cg2(tmem + 256, dA + ko, dB + NH + ko, acc);  // N[256:512)
                }
            } else {
                #pragma unroll
                for (int ks = 0; ks < 4; ks++) {
                    const uint64_t ko = (uint64_t)(ks * 2);   // +32B = 32 e4m3 K-elems
                    mma_f8_cg2(tmem +   0, dA + ko, dB + ko,      1u);
                    mma_f8_cg2(tmem + 256, dA + ko, dB + NH + ko, 1u);
                }
            }
            tcommit_cg2_mc(CB + s * 8);   // releases stage s in BOTH CTAs on retire
        }
        tcommit_cg2_mc(FINAL);
    }

    mbar_wait(FINAL, 0);
    asm volatile("tcgen05.fence::after_thread_sync;" ::: "memory");

    // ---- epilogue: this CTA's 128 rows x 512 cols, in two 256-col chunks ----
    const int r = wid * 32 + lid;
    uint32_t* epi = (uint32_t*)(smem + SMEM_STAGE0);   // 128KB staging (stages dead)
    const float scale = 0.022097086912079608f;         // 1/sqrt(2048)

    #pragma unroll
    for (int nh = 0; nh < 2; nh++) {
        #pragma unroll
        for (int cb = 0; cb < 256; cb += 32) {
            uint32_t regs[32];
            TLD_32X32B_X32(regs, tmem + nh * 256 + cb);
            asm volatile("tcgen05.wait::ld.sync.aligned;" ::: "memory");
            #pragma unroll
            for (int j = 0; j < 32; j++) {
                const int c = cb + j;
                epi[r * 256 + (c ^ (r & 31))] = regs[j];
            }
        }
        __syncthreads();

        float* outBase = out + (size_t)(tm * TMP + rank * TMSUB) * D_OUT
                       + (size_t)tn * TNP + nh * 256;
        const float* bch = bias + tn * TNP + nh * 256;
        #pragma unroll 4
        for (int itl = 0; itl < (TMSUB * 256) / 128; itl++) {
            const int i = itl * 128 + tid;
            const int rr = i >> 8;
            const int c = i & 255;
            const float v = __uint_as_float(epi[rr * 256 + (c ^ (rr & 31))]);
            outBase[(size_t)rr * D_OUT + c] = v * scale + 0.1f * __ldg(bch + c);
        }
        __syncthreads();
    }

    if (wid == 0) {
        asm volatile("tcgen05.dealloc.cta_group::2.sync.aligned.b32 %0, %1;"
                     :: "r"(tmem), "r"(TMEM_COLS));
    }
    // no CTA exits while its SMEM may still be referenced by the pair
    asm volatile("barrier.cluster.arrive.aligned;" ::: "memory");
    asm volatile("barrier.cluster.wait.aligned;" ::: "memory");

#else  // ======================= SIMT fp32 fallback =========================
    extern __shared__ __align__(16) float fsm[];
    float* ws = fsm;                 // 32 cols x 128 k  (16 KB)
    float* xs = fsm + 32 * 128;      // 128 rows x 132   (66 KB)
    const int tid = threadIdx.x;
    const int tn = blockIdx.x >> 1, rk = blockIdx.x & 1, tm = blockIdx.y;
    const float scale = 0.022097086912079608f;
    const int rowBase = tm * TMP + rk * TMSUB;
    const int row = rowBase + tid;

    for (int nc = 0; nc < TNP / 32; nc++) {
        const int cb = tn * TNP + nc * 32;
        float acc[32];
        #pragma unroll
        for (int c = 0; c < 32; c++) acc[c] = 0.0f;

        for (int kb = 0; kb < D_IN; kb += 128) {
            __syncthreads();
            for (int i = tid; i < 32 * 128; i += 128)
                ws[i] = w[(size_t)(cb + (i >> 7)) * D_IN + kb + (i & 127)];
            for (int i = tid; i < 128 * 128; i += 128)
                xs[(i >> 7) * 132 + (i & 127)] = x[(size_t)(rowBase + (i >> 7)) * D_IN + kb + (i & 127)];
            __syncthreads();

            #pragma unroll 2
            for (int k4 = 0; k4 < 32; k4++) {
                const float4 xv = *(const float4*)&xs[tid * 132 + k4 * 4];
                #pragma unroll
                for (int c = 0; c < 32; c++) {
                    const float4 wv = *(const float4*)&ws[(c << 7) + (k4 << 2)];
                    acc[c] += xv.x * wv.x + xv.y * wv.y + xv.z * wv.z + xv.w * wv.w;
                }
            }
        }
        #pragma unroll
        for (int c = 0; c < 32; c++)
            out[(size_t)row * D_OUT + cb + c] = acc[c] * scale + 0.1f * bias[cb + c];
    }
#endif
}

// ============================================================================
extern "C" void kernel_launch(void* const* d_in, const int* in_sizes, int n_in,
                              void* d_out, int out_size) {
    const float* x = (const float*)d_in[0];
    const float* w = (const float*)d_in[1];
    const float* b = (const float*)d_in[2];
    float* out = (float*)d_out;

    cudaFuncSetAttribute(gemm_kernel, cudaFuncAttributeMaxDynamicSharedMemorySize, SMEM_TOTAL);

    convert_kernel<TMSUB, 0><<<dim3(D_IN / 128, N_ROWS / TMSUB), 256>>>(x);  // x -> g_X
    convert_kernel<TNP, 1> <<<dim3(D_IN / 128, D_OUT / TNP),     256>>>(w);  // W -> g_W (perm)
    gemm_kernel<<<dim3((D_OUT / TNP) * 2, N_ROWS / TMP), 128, SMEM_TOTAL>>>(x, w, b, out);
}